// round 16
// baseline (speedup 1.0000x reference)
#include <cuda_runtime.h>
#include <math.h>

// Problem: out[b,c] = M @ X[b,c] @ M^T  per channel, where
// M[m,n] = (1/960) * [1 + S(a+b) + S(a-b)],
//   a = pi(2n+1)/1536, b = pi(2m+1)/1920,
//   S(c) = sum_{k=1}^{767} cos(kc) = sin(767.5 c)/(2 sin(c/2)) - 1/2.
// This is the exact composition idct_960(pad(dct_768(.))) along one axis.

#define HN    768
#define HOUT  960
#define NCH   48

#define BM 128
#define BN 128
#define BK 8
#define TM 8
#define TN 8
#define NTHREADS 256

// Scratch (allocation-free rule: device globals only)
__device__ float g_M[HOUT * HN];                    // 960 x 768  (~2.95 MB)
__device__ float g_T[(size_t)NCH * HOUT * HN];      // 48 x 960 x 768 (~141.6 MB)

// ---------------------------------------------------------------------------
// Generate the composed resize matrix M in double precision (closed form).
// ---------------------------------------------------------------------------
__global__ void gen_M_kernel() {
    int idx = blockIdx.x * blockDim.x + threadIdx.x;
    if (idx >= HOUT * HN) return;
    int m = idx / HN;
    int n = idx - m * HN;
    const double PI = 3.14159265358979323846;
    double a = PI * (2.0 * (double)n + 1.0) / (2.0 * (double)HN);    // /1536
    double b = PI * (2.0 * (double)m + 1.0) / (2.0 * (double)HOUT);  // /1920
    double cp = a + b;
    double cm = a - b;          // never 0 mod 2*pi (5(2n+1) - 4(2m+1) is odd)
    double Kh = (double)HN - 0.5;  // 767.5
    double s1 = sin(Kh * cp) / (2.0 * sin(0.5 * cp)) - 0.5;
    double s2 = sin(Kh * cm) / (2.0 * sin(0.5 * cm)) - 0.5;
    g_M[idx] = (float)((1.0 + s1 + s2) / (double)HOUT);
}

// ---------------------------------------------------------------------------
// SGEMM core: C[M,N] = A[M,K] * op(B), op(B) = B[K,N] (NN) or B[N,K]^T (NT).
// 128x128 tile, BK=8, 8x8 per-thread microtile, float4 everywhere.
// K must be a multiple of 8 (768 ✓). N must be a multiple of 8 (768/960 ✓).
// ---------------------------------------------------------------------------
template<bool BNT>
__device__ __forceinline__ void gemm_core(const float* __restrict__ A,
                                          const float* __restrict__ B,
                                          float* __restrict__ C,
                                          int M, int N, int K)
{
    __shared__ float As[BK][BM];
    __shared__ float Bs[BK][BN];

    const int tid   = threadIdx.x;
    const int tileM = blockIdx.y * BM;
    const int tileN = blockIdx.x * BN;

    // A (and NT-B) loader mapping: one float4 along K per thread
    const int aRow = tid >> 1;            // 0..127
    const int aCol = (tid & 1) << 2;      // 0 or 4
    // NN-B loader mapping: one float4 along N per thread
    const int bRowNN = tid >> 5;          // 0..7 (k)
    const int bColNN = (tid & 31) << 2;   // 0..124

    const int tRow = (tid >> 4) * TM;     // 0..120
    const int tCol = (tid & 15) * TN;     // 0..120

    float acc[TM][TN];
    #pragma unroll
    for (int i = 0; i < TM; i++)
        #pragma unroll
        for (int j = 0; j < TN; j++) acc[i][j] = 0.f;

    for (int k0 = 0; k0 < K; k0 += BK) {
        // ---- stage A tile (transposed into As[k][m]) ----
        {
            int gr = tileM + aRow;
            float4 v = make_float4(0.f, 0.f, 0.f, 0.f);
            if (gr < M)
                v = *reinterpret_cast<const float4*>(A + (size_t)gr * K + k0 + aCol);
            As[aCol + 0][aRow] = v.x;
            As[aCol + 1][aRow] = v.y;
            As[aCol + 2][aRow] = v.z;
            As[aCol + 3][aRow] = v.w;
        }
        // ---- stage B tile ----
        if (BNT) {
            // B is [N,K] row-major; need Bs[k][n] = B[n][k]
            int gn = tileN + aRow;
            float4 v = make_float4(0.f, 0.f, 0.f, 0.f);
            if (gn < N)
                v = *reinterpret_cast<const float4*>(B + (size_t)gn * K + k0 + aCol);
            Bs[aCol + 0][aRow] = v.x;
            Bs[aCol + 1][aRow] = v.y;
            Bs[aCol + 2][aRow] = v.z;
            Bs[aCol + 3][aRow] = v.w;
        } else {
            // B is [K,N] row-major; direct float4 copy
            int gc = tileN + bColNN;
            float4 v = make_float4(0.f, 0.f, 0.f, 0.f);
            if (gc < N)
                v = *reinterpret_cast<const float4*>(B + (size_t)(k0 + bRowNN) * N + gc);
            *reinterpret_cast<float4*>(&Bs[bRowNN][bColNN]) = v;
        }
        __syncthreads();

        // ---- compute: 8 k-steps of 8x8 FFMA ----
        #pragma unroll
        for (int k = 0; k < BK; k++) {
            float4 a0 = *reinterpret_cast<const float4*>(&As[k][tRow]);
            float4 a1 = *reinterpret_cast<const float4*>(&As[k][tRow + 4]);
            float4 b0 = *reinterpret_cast<const float4*>(&Bs[k][tCol]);
            float4 b1 = *reinterpret_cast<const float4*>(&Bs[k][tCol + 4]);
            float ra[TM] = {a0.x, a0.y, a0.z, a0.w, a1.x, a1.y, a1.z, a1.w};
            float rb[TN] = {b0.x, b0.y, b0.z, b0.w, b1.x, b1.y, b1.z, b1.w};
            #pragma unroll
            for (int i = 0; i < TM; i++)
                #pragma unroll
                for (int j = 0; j < TN; j++)
                    acc[i][j] = fmaf(ra[i], rb[j], acc[i][j]);
        }
        __syncthreads();
    }

    // ---- epilogue: guarded float4 stores (gc 8-aligned, N % 8 == 0) ----
    #pragma unroll
    for (int i = 0; i < TM; i++) {
        int gr = tileM + tRow + i;
        if (gr >= M) continue;
        int gc = tileN + tCol;
        if (gc >= N) continue;
        float4 v0 = make_float4(acc[i][0], acc[i][1], acc[i][2], acc[i][3]);
        float4 v1 = make_float4(acc[i][4], acc[i][5], acc[i][6], acc[i][7]);
        *reinterpret_cast<float4*>(C + (size_t)gr * N + gc)     = v0;
        *reinterpret_cast<float4*>(C + (size_t)gr * N + gc + 4) = v1;
    }
}

// Step A: T[c] = M(960x768) @ X[c](768x768)           (NN)
__global__ __launch_bounds__(NTHREADS, 2)
void gemmA_kernel(const float* __restrict__ x) {
    int c = blockIdx.z;
    const float* B = x + (size_t)c * HN * HN;
    float* Cc = g_T + (size_t)c * HOUT * HN;
    gemm_core<false>(g_M, B, Cc, HOUT, HN, HN);
}

// Step B: out[c] = T[c](960x768) @ M^T(768x960)       (NT, B = M row-major [960x768])
__global__ __launch_bounds__(NTHREADS, 2)
void gemmB_kernel(float* __restrict__ out) {
    int c = blockIdx.z;
    const float* Ac = g_T + (size_t)c * HOUT * HN;
    float* Cc = out + (size_t)c * HOUT * HOUT;
    gemm_core<true>(Ac, g_M, Cc, HOUT, HOUT, HN);
}

extern "C" void kernel_launch(void* const* d_in, const int* in_sizes, int n_in,
                              void* d_out, int out_size) {
    const float* x = (const float*)d_in[0];   // [16,3,768,768] = [48,768,768]
    float* out = (float*)d_out;               // [16,3,960,960]

    // 1. Build M (closed-form Dirichlet sums, double precision)
    gen_M_kernel<<<(HOUT * HN + 255) / 256, 256>>>();

    // 2. T = M @ X   : grid (768/128=6, ceil(960/128)=8, 48)
    dim3 gridA(HN / BN, (HOUT + BM - 1) / BM, NCH);
    gemmA_kernel<<<gridA, NTHREADS>>>(x);

    // 3. out = T @ M^T : grid (8, 8, 48)
    dim3 gridB((HOUT + BN - 1) / BN, (HOUT + BM - 1) / BM, NCH);
    gemmB_kernel<<<gridB, NTHREADS>>>(out);
}

// round 17
// speedup vs baseline: 1.0009x; 1.0009x over previous
#include <cuda_runtime.h>
#include <math.h>

// Problem: out[b,c] = M @ X[b,c] @ M^T  per channel, where
// M[m,n] = (1/960) * [1 + S(a+b) + S(a-b)],
//   a = pi(2n+1)/1536, b = pi(2m+1)/1920,
//   S(c) = sum_{k=1}^{767} cos(kc) = sin(767.5 c)/(2 sin(c/2)) - 1/2.
// This is the exact composition idct_960(pad(dct_768(.))) along one axis.

#define HN    768
#define HOUT  960
#define NCH   48

#define BM 128
#define BN 128
#define BK 8
#define TM 8
#define TN 8
#define NTHREADS 256

// Scratch (allocation-free rule: device globals only)
__device__ float g_M[HOUT * HN];                    // 960 x 768  (~2.95 MB)
__device__ float g_T[(size_t)NCH * HOUT * HN];      // 48 x 960 x 768 (~141.6 MB)

// ---------------------------------------------------------------------------
// Generate the composed resize matrix M in double precision (closed form).
// ---------------------------------------------------------------------------
__global__ void gen_M_kernel() {
    int idx = blockIdx.x * blockDim.x + threadIdx.x;
    if (idx >= HOUT * HN) return;
    int m = idx / HN;
    int n = idx - m * HN;
    const double PI = 3.14159265358979323846;
    double a = PI * (2.0 * (double)n + 1.0) / (2.0 * (double)HN);    // /1536
    double b = PI * (2.0 * (double)m + 1.0) / (2.0 * (double)HOUT);  // /1920
    double cp = a + b;
    double cm = a - b;          // never 0 mod 2*pi (5(2n+1) - 4(2m+1) is odd)
    double Kh = (double)HN - 0.5;  // 767.5
    double s1 = sin(Kh * cp) / (2.0 * sin(0.5 * cp)) - 0.5;
    double s2 = sin(Kh * cm) / (2.0 * sin(0.5 * cm)) - 0.5;
    g_M[idx] = (float)((1.0 + s1 + s2) / (double)HOUT);
}

// ---------------------------------------------------------------------------
// SGEMM core: C[M,N] = A[M,K] * op(B), op(B) = B[K,N] (NN) or B[N,K]^T (NT).
// 128x128 tile, BK=8, 8x8 per-thread microtile, float4 everywhere.
// K must be a multiple of 8 (768 ✓). N must be a multiple of 8 (768/960 ✓).
// ---------------------------------------------------------------------------
template<bool BNT>
__device__ __forceinline__ void gemm_core(const float* __restrict__ A,
                                          const float* __restrict__ B,
                                          float* __restrict__ C,
                                          int M, int N, int K)
{
    __shared__ float As[BK][BM];
    __shared__ float Bs[BK][BN];

    const int tid   = threadIdx.x;
    const int tileM = blockIdx.y * BM;
    const int tileN = blockIdx.x * BN;

    // A (and NT-B) loader mapping: one float4 along K per thread
    const int aRow = tid >> 1;            // 0..127
    const int aCol = (tid & 1) << 2;      // 0 or 4
    // NN-B loader mapping: one float4 along N per thread
    const int bRowNN = tid >> 5;          // 0..7 (k)
    const int bColNN = (tid & 31) << 2;   // 0..124

    const int tRow = (tid >> 4) * TM;     // 0..120
    const int tCol = (tid & 15) * TN;     // 0..120

    float acc[TM][TN];
    #pragma unroll
    for (int i = 0; i < TM; i++)
        #pragma unroll
        for (int j = 0; j < TN; j++) acc[i][j] = 0.f;

    for (int k0 = 0; k0 < K; k0 += BK) {
        // ---- stage A tile (transposed into As[k][m]) ----
        {
            int gr = tileM + aRow;
            float4 v = make_float4(0.f, 0.f, 0.f, 0.f);
            if (gr < M)
                v = *reinterpret_cast<const float4*>(A + (size_t)gr * K + k0 + aCol);
            As[aCol + 0][aRow] = v.x;
            As[aCol + 1][aRow] = v.y;
            As[aCol + 2][aRow] = v.z;
            As[aCol + 3][aRow] = v.w;
        }
        // ---- stage B tile ----
        if (BNT) {
            // B is [N,K] row-major; need Bs[k][n] = B[n][k]
            int gn = tileN + aRow;
            float4 v = make_float4(0.f, 0.f, 0.f, 0.f);
            if (gn < N)
                v = *reinterpret_cast<const float4*>(B + (size_t)gn * K + k0 + aCol);
            Bs[aCol + 0][aRow] = v.x;
            Bs[aCol + 1][aRow] = v.y;
            Bs[aCol + 2][aRow] = v.z;
            Bs[aCol + 3][aRow] = v.w;
        } else {
            // B is [K,N] row-major; direct float4 copy
            int gc = tileN + bColNN;
            float4 v = make_float4(0.f, 0.f, 0.f, 0.f);
            if (gc < N)
                v = *reinterpret_cast<const float4*>(B + (size_t)(k0 + bRowNN) * N + gc);
            *reinterpret_cast<float4*>(&Bs[bRowNN][bColNN]) = v;
        }
        __syncthreads();

        // ---- compute: 8 k-steps of 8x8 FFMA ----
        #pragma unroll
        for (int k = 0; k < BK; k++) {
            float4 a0 = *reinterpret_cast<const float4*>(&As[k][tRow]);
            float4 a1 = *reinterpret_cast<const float4*>(&As[k][tRow + 4]);
            float4 b0 = *reinterpret_cast<const float4*>(&Bs[k][tCol]);
            float4 b1 = *reinterpret_cast<const float4*>(&Bs[k][tCol + 4]);
            float ra[TM] = {a0.x, a0.y, a0.z, a0.w, a1.x, a1.y, a1.z, a1.w};
            float rb[TN] = {b0.x, b0.y, b0.z, b0.w, b1.x, b1.y, b1.z, b1.w};
            #pragma unroll
            for (int i = 0; i < TM; i++)
                #pragma unroll
                for (int j = 0; j < TN; j++)
                    acc[i][j] = fmaf(ra[i], rb[j], acc[i][j]);
        }
        __syncthreads();
    }

    // ---- epilogue: guarded float4 stores (gc 8-aligned, N % 8 == 0) ----
    #pragma unroll
    for (int i = 0; i < TM; i++) {
        int gr = tileM + tRow + i;
        if (gr >= M) continue;
        int gc = tileN + tCol;
        if (gc >= N) continue;
        float4 v0 = make_float4(acc[i][0], acc[i][1], acc[i][2], acc[i][3]);
        float4 v1 = make_float4(acc[i][4], acc[i][5], acc[i][6], acc[i][7]);
        *reinterpret_cast<float4*>(C + (size_t)gr * N + gc)     = v0;
        *reinterpret_cast<float4*>(C + (size_t)gr * N + gc + 4) = v1;
    }
}

// Step A: T[c] = M(960x768) @ X[c](768x768)           (NN)
__global__ __launch_bounds__(NTHREADS, 2)
void gemmA_kernel(const float* __restrict__ x) {
    int c = blockIdx.z;
    const float* B = x + (size_t)c * HN * HN;
    float* Cc = g_T + (size_t)c * HOUT * HN;
    gemm_core<false>(g_M, B, Cc, HOUT, HN, HN);
}

// Step B: out[c] = T[c](960x768) @ M^T(768x960)       (NT, B = M row-major [960x768])
__global__ __launch_bounds__(NTHREADS, 2)
void gemmB_kernel(float* __restrict__ out) {
    int c = blockIdx.z;
    const float* Ac = g_T + (size_t)c * HOUT * HN;
    float* Cc = out + (size_t)c * HOUT * HOUT;
    gemm_core<true>(Ac, g_M, Cc, HOUT, HOUT, HN);
}

extern "C" void kernel_launch(void* const* d_in, const int* in_sizes, int n_in,
                              void* d_out, int out_size) {
    const float* x = (const float*)d_in[0];   // [16,3,768,768] = [48,768,768]
    float* out = (float*)d_out;               // [16,3,960,960]

    // 1. Build M (closed-form Dirichlet sums, double precision)
    gen_M_kernel<<<(HOUT * HN + 255) / 256, 256>>>();

    // 2. T = M @ X   : grid (768/128=6, ceil(960/128)=8, 48)
    dim3 gridA(HN / BN, (HOUT + BM - 1) / BM, NCH);
    gemmA_kernel<<<gridA, NTHREADS>>>(x);

    // 3. out = T @ M^T : grid (8, 8, 48)
    dim3 gridB((HOUT + BN - 1) / BN, (HOUT + BM - 1) / BM, NCH);
    gemmB_kernel<<<gridB, NTHREADS>>>(out);
}